// round 17
// baseline (speedup 1.0000x reference)
#include <cuda_runtime.h>
#include <cuda_fp16.h>
#include <cstdint>

#define H       128
#define NHEAD   8
#define N_MAX   50000
#define E_MAX   800000
#define NRELMX  64
#define TILE_E  64
#define NT      256

// ---------------- global scratch -------------------------------------------
__device__ float g_Q  [N_MAX * H];
__device__ float g_S1 [N_MAX * H];
__device__ float g_R2x[NRELMX * H];
__device__ float g_denom[N_MAX * NHEAD];
__device__ __half g_B [256 * H];       // [Wk|Wv] image, 256B rows, XOR-16B swizzle
__device__ __half g_BN[256 * H];       // [Wq|W1a] image, same format
__device__ int   g_hist[N_MAX];        // zero at module load; re-zeroed by k_norm
__device__ int   g_offs[N_MAX + 1];
__device__ int   g_offsw[N_MAX];
__device__ int   g_perm[E_MAX];

// ---------------- smem layout (edge kernel, NT=256) ------------------------
#define OFF_B     0        // 65536
#define OFF_A     65536    // 16384 (fp16 A tile, 64 x 256B)
#define OFF_KV    65536    // 32768 (aliases A; 64 x 512B fp32 rows)
#define OFF_BK    98304
#define OFF_BV    98816
#define OFF_B1    99328
#define OFF_W2    99840
#define OFF_DST   100352   // 256
#define OFF_SS    100608   // 256
#define OFF_WS    100864   // w_sm[64][8] = 2048
#define OFF_SEG   102912   // 64 ints
#define OFF_NSEG  103168
#define SMEM_EDGE 103424

// node kernel smem (NT=512 kernel)
#define NOFF_B    0
#define NOFF_A    65536    // 32768
#define NOFF_KV   65536    // 65536 alias
#define NOFF_BQ   131072
#define SMEM_NODE 131584
#define NTN       512

// ---------------- helpers --------------------------------------------------
__device__ __forceinline__ uint32_t s2u(const void* p) {
    uint32_t a;
    asm("{ .reg .u64 t; cvta.to.shared.u64 t, %1; cvt.u32.u64 %0, t; }" : "=r"(a) : "l"(p));
    return a;
}
__device__ __forceinline__ void ldsm4(uint32_t* r, uint32_t addr) {
    asm volatile("ldmatrix.sync.aligned.m8n8.x4.shared.b16 {%0,%1,%2,%3}, [%4];"
                 : "=r"(r[0]), "=r"(r[1]), "=r"(r[2]), "=r"(r[3]) : "r"(addr));
}
__device__ __forceinline__ void mma16816(float* c, const uint32_t* a, const uint32_t* b) {
    asm volatile(
        "mma.sync.aligned.m16n8k16.row.col.f32.f16.f16.f32 "
        "{%0,%1,%2,%3}, {%4,%5,%6,%7}, {%8,%9}, {%0,%1,%2,%3};"
        : "+f"(c[0]), "+f"(c[1]), "+f"(c[2]), "+f"(c[3])
        : "r"(a[0]), "r"(a[1]), "r"(a[2]), "r"(a[3]), "r"(b[0]), "r"(b[1]));
}
#define REDV4(p, a, b, c, d) asm volatile("red.global.add.v4.f32 [%0], {%1,%2,%3,%4};" :: "l"(p), "f"(a), "f"(b), "f"(c), "f"(d) : "memory")

// ---------------- pre1: zero out+denom, histogram dst ----------------------
__global__ void k_pre1(const int* __restrict__ dst, float* __restrict__ out,
                       int N, int E, int outElems) {
    int i = blockIdx.x * blockDim.x + threadIdx.x;
    int stride = gridDim.x * blockDim.x;
    for (int idx = i; idx < outElems; idx += stride) out[idx] = 0.f;
    for (int idx = i; idx < N * NHEAD; idx += stride) g_denom[idx] = 0.f;
    for (int idx = i; idx < E; idx += stride) atomicAdd(&g_hist[dst[idx]], 1);
}

// ---------------- scan: exclusive prefix over hist (1 CTA) -----------------
__global__ void __launch_bounds__(1024) k_scan(int N, int E) {
    __shared__ int sm[1024];
    int t = threadIdx.x;
    int chunk = (N + 1023) >> 10;
    int base = t * chunk;
    int s = 0;
    for (int i = 0; i < chunk; i++) {
        int ix = base + i;
        if (ix < N) s += g_hist[ix];
    }
    sm[t] = s;
    __syncthreads();
    for (int off = 1; off < 1024; off <<= 1) {
        int v = (t >= off) ? sm[t - off] : 0;
        __syncthreads();
        sm[t] += v;
        __syncthreads();
    }
    int run = sm[t] - s;
    for (int i = 0; i < chunk; i++) {
        int ix = base + i;
        if (ix < N) {
            g_offs[ix] = run;
            g_offsw[ix] = run;
            run += g_hist[ix];
        }
    }
    if (t == 0) g_offs[N] = E;
}

// ---------------- pre3: scatter-perm + weight images + R2x -----------------
__global__ void k_pre3(
    const int* __restrict__ dst,
    const float* __restrict__ Wq, const float* __restrict__ W1,
    const float* __restrict__ rel,
    const float* __restrict__ Wk, const float* __restrict__ Wv,
    int N, int E, int NREL, int NB_SC, int NB_PW)
{
    int b = blockIdx.x, tid = threadIdx.x;
    if (b < NB_SC) {
        int e = b * 256 + tid;
        if (e < E) {
            int d = dst[e];
            int pos = atomicAdd(&g_offsw[d], 1);
            g_perm[pos] = e;
        }
        return;
    }
    b -= NB_SC;
    if (b < NB_PW) {
        int n = b * 2 + (tid >> 7);
        int k = tid & 127;
        unsigned kb = (unsigned)k * 2u;
        if (n < 256) {
            float w = (n < H) ? Wk[k * H + n] : Wv[k * H + (n - H)];
            unsigned phys = (unsigned)n * 256u + (kb ^ ((unsigned)(n & 7) << 4));
            *(__half*)((char*)g_B + phys) = __float2half_rn(w);
        } else {
            int m = n - 256;
            float w = (m < H) ? Wq[k * H + m] : W1[k * H + (m - H)];
            unsigned phys = (unsigned)m * 256u + (kb ^ ((unsigned)(m & 7) << 4));
            *(__half*)((char*)g_BN + phys) = __float2half_rn(w);
        }
        return;
    }
    b -= NB_PW;
    {
        int r = b * 2 + (tid >> 7);
        int j = tid & 127;
        if (r < NREL) {
            float acc = W1[256 * H + j];
            for (int i = 0; i < H; i++)
                acc += rel[r * H + i] * W1[(H + i) * H + j];
            g_R2x[r * H + j] = acc;
        }
    }
}

// ---------------- node GEMM: Q = x@Wq+bq, S1 = x@W1a (fp16 mma) ------------
__global__ void __launch_bounds__(NTN, 1) k_nodemma(
    const float* __restrict__ x, const float* __restrict__ bq, int N)
{
    extern __shared__ __align__(1024) char smc[];
    uint32_t smb = s2u(smc);
    int tid = threadIdx.x, wid = tid >> 5, lane = tid & 31;

    {
        float4* d0 = (float4*)(smc + NOFF_B);
        const float4* s0 = (const float4*)g_BN;
        for (int i = tid; i < 4096; i += NTN) d0[i] = s0[i];
    }
    if (tid < H) ((float*)(smc + NOFF_BQ))[tid] = bq[tid];
    __syncthreads();

    int n0t = blockIdx.x * 128;
    int cnt = min(128, N - n0t);

    int warp_row = wid & 1;
    int warp_col = wid >> 1;
    int n0 = warp_col * 32;
    bool isQ = (n0 < 128);

    int ra = lane & 7, ha = (lane >> 3) & 1, kh = lane >> 4;
    uint32_t aXor = (uint32_t)ra << 4;
    uint32_t aKh = (uint32_t)(kh * 16);
    uint32_t aRowBase = smb + NOFF_A + (uint32_t)(warp_row * 64 + ha * 8 + ra) * 256u;

    int qb = lane >> 3, rb = lane & 7;
    uint32_t bXor = (uint32_t)rb << 4;
    uint32_t bKh = (uint32_t)((qb & 1) * 16);
    uint32_t bRow0 = smb + NOFF_B + (uint32_t)(n0 + (qb >> 1) * 8 + rb) * 256u;
    uint32_t bRow1 = bRow0 + 16u * 256u;

    int r4 = lane >> 2, c2 = (lane & 3) * 2;
    int ew0 = wid * 8;

#pragma unroll
    for (int e = 0; e < 8; e++) {
        int ge = ew0 + e;
        int row = (ge < cnt) ? (n0t + ge) : n0t;
        float4 xv = __ldg((const float4*)(x + (size_t)row * H) + lane);
        __half2 h01 = __floats2half2_rn(xv.x, xv.y);
        __half2 h23 = __floats2half2_rn(xv.z, xv.w);
        char* Ah = smc + NOFF_A + ge * 256;
        unsigned kb = (unsigned)(lane * 8);
        unsigned xr = (unsigned)(ge & 7) << 4;
        uint2 uh; uh.x = *(unsigned*)&h01; uh.y = *(unsigned*)&h23;
        *(uint2*)(Ah + (kb ^ xr)) = uh;
    }
    __syncthreads();

    float acc[4][4][4];
#pragma unroll
    for (int mt = 0; mt < 4; mt++)
#pragma unroll
        for (int ng = 0; ng < 4; ng++)
#pragma unroll
            for (int i = 0; i < 4; i++) acc[mt][ng][i] = 0.f;

    for (int ks = 0; ks < 8; ks++) {
        uint32_t kbB = ((uint32_t)(ks * 32) + bKh) ^ bXor;
        uint32_t bh[8];
        ldsm4(bh + 0, bRow0 + kbB);
        ldsm4(bh + 4, bRow1 + kbB);
        uint32_t kbA = ((uint32_t)(ks * 32) + aKh) ^ aXor;
#pragma unroll
        for (int mt = 0; mt < 4; mt++) {
            uint32_t ah[4];
            ldsm4(ah, aRowBase + (uint32_t)(mt * 16) * 256u + kbA);
#pragma unroll
            for (int ng = 0; ng < 4; ng++)
                mma16816(acc[mt][ng], ah, bh + ng * 2);
        }
    }
    __syncthreads();

    float4 bq4 = *(const float4*)((float*)(smc + NOFF_BQ) + lane * 4);

    if (isQ) {
#pragma unroll
        for (int mt = 0; mt < 4; mt++) {
#pragma unroll
            for (int ng = 0; ng < 4; ng++) {
                int ee = warp_row * 64 + mt * 16 + r4;
                unsigned jb = (unsigned)((n0 + ng * 8 + c2) * 4);
                char* base = smc + NOFF_KV;
                *(float2*)(base + ee * 512 + (jb ^ ((unsigned)(ee & 31) << 4))) =
                    make_float2(acc[mt][ng][0], acc[mt][ng][1]);
                int ee2 = ee + 8;
                *(float2*)(base + ee2 * 512 + (jb ^ ((unsigned)(ee2 & 31) << 4))) =
                    make_float2(acc[mt][ng][2], acc[mt][ng][3]);
            }
        }
    }
    __syncthreads();
#pragma unroll
    for (int e = 0; e < 8; e++) {
        int ge = ew0 + e;
        if (ge < cnt) {
            char* krow = smc + NOFF_KV + ge * 512;
            float4 v = *(float4*)(krow + (((unsigned)(lane * 16)) ^ ((unsigned)(ge & 31) << 4)));
            v.x += bq4.x; v.y += bq4.y; v.z += bq4.z; v.w += bq4.w;
            *(float4*)(g_Q + (size_t)(n0t + ge) * H + lane * 4) = v;
        }
    }
    __syncthreads();

    if (!isQ) {
#pragma unroll
        for (int mt = 0; mt < 4; mt++) {
#pragma unroll
            for (int ng = 0; ng < 4; ng++) {
                int ee = warp_row * 64 + mt * 16 + r4;
                unsigned jb = (unsigned)((n0 - 128 + ng * 8 + c2) * 4);
                char* base = smc + NOFF_KV;
                *(float2*)(base + ee * 512 + (jb ^ ((unsigned)(ee & 31) << 4))) =
                    make_float2(acc[mt][ng][0], acc[mt][ng][1]);
                int ee2 = ee + 8;
                *(float2*)(base + ee2 * 512 + (jb ^ ((unsigned)(ee2 & 31) << 4))) =
                    make_float2(acc[mt][ng][2], acc[mt][ng][3]);
            }
        }
    }
    __syncthreads();
#pragma unroll
    for (int e = 0; e < 8; e++) {
        int ge = ew0 + e;
        if (ge < cnt) {
            char* vrow = smc + NOFF_KV + ge * 512;
            float4 v = *(float4*)(vrow + (((unsigned)(lane * 16)) ^ ((unsigned)(ge & 31) << 4)));
            *(float4*)(g_S1 + (size_t)(n0t + ge) * H + lane * 4) = v;
        }
    }
}

// ---------------- persistent fused edge kernel (2 CTAs/SM) -----------------
__global__ void __launch_bounds__(NT, 2) k_edge_mma(
    const float* __restrict__ x, const float* __restrict__ ts,
    const int* __restrict__ src, const int* __restrict__ dst, const int* __restrict__ et,
    const float* __restrict__ etime, const float* __restrict__ rel,
    const float* __restrict__ bk, const float* __restrict__ bv,
    const float* __restrict__ b1, const float* __restrict__ W2,
    const float* __restrict__ b2, const float* __restrict__ tcp,
    float* __restrict__ out, int E, int ntiles)
{
    extern __shared__ __align__(1024) char smc[];
    uint32_t smb = s2u(smc);
    int tid = threadIdx.x, wid = tid >> 5, lane = tid & 31;

    float* bk_s  = (float*)(smc + OFF_BK);
    float* bv_s  = (float*)(smc + OFF_BV);
    float* b1_s  = (float*)(smc + OFF_B1);
    float* w2_s  = (float*)(smc + OFF_W2);
    int*   dst_s = (int*)  (smc + OFF_DST);
    float* ss_s  = (float*)(smc + OFF_SS);
    float* w_sm  = (float*)(smc + OFF_WS);
    int*   seg_s = (int*)  (smc + OFF_SEG);
    int*   nseg_p= (int*)  (smc + OFF_NSEG);

    {
        float4* d0 = (float4*)(smc + OFF_B);
        const float4* s0 = (const float4*)g_B;
        for (int i = tid; i < 4096; i += NT) d0[i] = s0[i];
    }
    if (tid < H) { bk_s[tid] = bk[tid]; bv_s[tid] = bv[tid]; b1_s[tid] = b1[tid]; w2_s[tid] = W2[tid]; }
    __syncthreads();

    float inv_tc = 1.f / (fabsf(tcp[0]) + 1e-9f);
    float b2v = b2[0];

    // ---- per-warp GEMM tiling: m64 x n32, 8 warps over n256 ----
    int n0 = wid * 32;
    bool isK = (n0 < 128);

    int ra = lane & 7, ha = (lane >> 3) & 1, kh = lane >> 4;
    uint32_t aXor = (uint32_t)ra << 4;
    uint32_t aKh = (uint32_t)(kh * 16);
    uint32_t aRowBase = smb + OFF_A + (uint32_t)(ha * 8 + ra) * 256u;

    int qb = lane >> 3, rb = lane & 7;
    uint32_t bXor = (uint32_t)rb << 4;
    uint32_t bKh = (uint32_t)((qb & 1) * 16);
    uint32_t bRow0 = smb + OFF_B + (uint32_t)(n0 + (qb >> 1) * 8 + rb) * 256u;
    uint32_t bRow1 = bRow0 + 16u * 256u;

    int r4 = lane >> 2, c2 = (lane & 3) * 2;
    int ew0 = wid * 8;

    float4 b14 = *(const float4*)(b1_s + lane * 4);
    float4 w24 = *(const float4*)(w2_s + lane * 4);
    float4 bk4 = *(const float4*)(bk_s + lane * 4);
    float4 bv4 = *(const float4*)(bv_s + lane * 4);
    int head = lane >> 2;

    for (int t = blockIdx.x; t < ntiles; t += gridDim.x) {
        int e0 = t * TILE_E;
        int cnt = min(TILE_E, E - e0);

        // ---- phase 1: meta + coalesced row gather + batched gating reduce ----
        {
            int sn = 0, rr = 0, dd = 0;
            float tme = 0.f;
            if (lane < 8) {
                int ge = ew0 + lane;
                if (ge < cnt) {
                    int ee = __ldg(&g_perm[e0 + ge]);
                    dd = dst[ee];
                    sn = src[ee]; rr = et[ee];
                    float dt = (ts[dd] - etime[ee]) * inv_tc;
                    tme = 1.f / (1.f + expf(-dt));
                }
                dst_s[ge] = dd;
            }
            float pe[8];
#pragma unroll
            for (int e = 0; e < 8; e++) {
                int ge = ew0 + e;
                int sne = __shfl_sync(0xFFFFFFFFu, sn, e);
                int rre = __shfl_sync(0xFFFFFFFFu, rr, e);
                float tmee = __shfl_sync(0xFFFFFFFFu, tme, e);
                float4 xv = __ldg((const float4*)(x     + (size_t)sne * H) + lane);
                float4 rv = __ldg((const float4*)(rel   + (size_t)rre * H) + lane);
                float4 s1 = __ldg((const float4*)(g_S1  + (size_t)sne * H) + lane);
                float4 r2 = __ldg((const float4*)(g_R2x + (size_t)rre * H) + lane);
                float g0 = xv.x * rv.x, g1 = xv.y * rv.y, g2 = xv.z * rv.z, g3 = xv.w * rv.w;
                float p;
                p  = fmaxf(fmaf(tmee, r2.x, s1.x + b14.x), 0.f) * w24.x;
                p += fmaxf(fmaf(tmee, r2.y, s1.y + b14.y), 0.f) * w24.y;
                p += fmaxf(fmaf(tmee, r2.z, s1.z + b14.z), 0.f) * w24.z;
                p += fmaxf(fmaf(tmee, r2.w, s1.w + b14.w), 0.f) * w24.w;
                pe[e] = p;
                __half2 h01 = __floats2half2_rn(g0, g1);
                __half2 h23 = __floats2half2_rn(g2, g3);
                char* Ah = smc + OFF_A + ge * 256;
                unsigned kb = (unsigned)(lane * 8);
                unsigned xr = (unsigned)(ge & 7) << 4;
                uint2 uh; uh.x = *(unsigned*)&h01; uh.y = *(unsigned*)&h23;
                *(uint2*)(Ah + (kb ^ xr)) = uh;
            }
#pragma unroll
            for (int off = 16; off >= 1; off >>= 1) {
#pragma unroll
                for (int e = 0; e < 8; e++)
                    pe[e] += __shfl_xor_sync(0xFFFFFFFFu, pe[e], off);
            }
            if (lane < 8) {
                float hsum = pe[0];
#pragma unroll
                for (int i = 1; i < 8; i++) hsum = (lane == i) ? pe[i] : hsum;
                float dw = 1.f / (1.f + expf(-(hsum + b2v)));
                ss_s[ew0 + lane] = tme * dw;
            }
        }
        if (tid == 0) nseg_p[0] = 0;
        __syncthreads();

        // ---- phase 2: GEMM 64x256x128 fp16, m64n32 per warp ----
        float acc[4][4][4];
#pragma unroll
        for (int mt = 0; mt < 4; mt++)
#pragma unroll
            for (int ng = 0; ng < 4; ng++)
#pragma unroll
                for (int i = 0; i < 4; i++) acc[mt][ng][i] = 0.f;

        for (int ks = 0; ks < 8; ks++) {
            uint32_t kbB = ((uint32_t)(ks * 32) + bKh) ^ bXor;
            uint32_t bh[8];
            ldsm4(bh + 0, bRow0 + kbB);
            ldsm4(bh + 4, bRow1 + kbB);
            uint32_t kbA = ((uint32_t)(ks * 32) + aKh) ^ aXor;
#pragma unroll
            for (int mt = 0; mt < 4; mt++) {
                uint32_t ah[4];
                ldsm4(ah, aRowBase + (uint32_t)(mt * 16) * 256u + kbA);
#pragma unroll
                for (int ng = 0; ng < 4; ng++)
                    mma16816(acc[mt][ng], ah, bh + ng * 2);
            }
        }
        __syncthreads();   // A free; KV aliases it

        // ---- phase 3: K-warps stage K; V-warps build segment list ----
        if (isK) {
#pragma unroll
            for (int mt = 0; mt < 4; mt++) {
#pragma unroll
                for (int ng = 0; ng < 4; ng++) {
                    int ee = mt * 16 + r4;
                    unsigned jb = (unsigned)((n0 + ng * 8 + c2) * 4);
                    char* base = smc + OFF_KV;
                    *(float2*)(base + ee * 512 + (jb ^ ((unsigned)(ee & 31) << 4))) =
                        make_float2(acc[mt][ng][0], acc[mt][ng][1]);
                    int ee2 = ee + 8;
                    *(float2*)(base + ee2 * 512 + (jb ^ ((unsigned)(ee2 & 31) << 4))) =
                        make_float2(acc[mt][ng][2], acc[mt][ng][3]);
                }
            }
        } else {
            int e = tid - 128;
            if (e >= 0 && e < TILE_E) {
                bool bnd = (e < cnt) && (e == 0 || dst_s[e] != dst_s[e - 1]);
                if (bnd) {
                    int s = atomicAdd(nseg_p, 1);
                    seg_s[s] = e;
                }
            }
        }
        __syncthreads();

        // ---- phase 4: scores, coalesced Q rows, warp per 8 edges ----
        {
#pragma unroll
            for (int e = 0; e < 8; e++) {
                int ge = ew0 + e;
                int d2 = dst_s[ge];
                float sce = ss_s[ge];
                float4 q4 = __ldg((const float4*)(g_Q + (size_t)d2 * H) + lane);
                char* kbase = smc + OFF_KV + ge * 512;
                float4 kr = *(float4*)(kbase + (((unsigned)(lane * 16)) ^ ((unsigned)(ge & 31) << 4)));
                float k0 = fmaf(kr.x, sce, bk4.x);
                float k1 = fmaf(kr.y, sce, bk4.y);
                float k2 = fmaf(kr.z, sce, bk4.z);
                float k3 = fmaf(kr.w, sce, bk4.w);
                float dp = q4.x * k0 + q4.y * k1 + q4.z * k2 + q4.w * k3;
                dp += __shfl_xor_sync(0xFFFFFFFFu, dp, 1);
                dp += __shfl_xor_sync(0xFFFFFFFFu, dp, 2);
                if ((lane & 3) == 0) w_sm[ge * 8 + head] = expf(dp * 0.25f);
            }
        }
        __syncthreads();

        int ns = nseg_p[0];

        // ---- phase 5: V-warps stage V; K-warps segmented denom ----
        if (!isK) {
#pragma unroll
            for (int mt = 0; mt < 4; mt++) {
#pragma unroll
                for (int ng = 0; ng < 4; ng++) {
                    int ee = mt * 16 + r4;
                    unsigned jb = (unsigned)((n0 - 128 + ng * 8 + c2) * 4);
                    char* base = smc + OFF_KV;
                    *(float2*)(base + ee * 512 + (jb ^ ((unsigned)(ee & 31) << 4))) =
                        make_float2(acc[mt][ng][0], acc[mt][ng][1]);
                    int ee2 = ee + 8;
                    *(float2*)(base + ee2 * 512 + (jb ^ ((unsigned)(ee2 & 31) << 4))) =
                        make_float2(acc[mt][ng][2], acc[mt][ng][3]);
                }
            }
        } else {
            for (int idx = tid; idx < ns * NHEAD; idx += 128) {
                int s = idx >> 3, h = idx & 7;
                int st = seg_s[s];
                int d = dst_s[st];
                int gs = __ldg(&g_offs[d]), gend = __ldg(&g_offs[d + 1]);
                int lend = min(cnt, gend - e0);
                float sum = 0.f;
                for (int e = st; e < lend; e++) sum += w_sm[e * 8 + h];
                bool interior = (gs >= e0) && (gend <= e0 + cnt);
                if (interior) g_denom[(size_t)d * NHEAD + h] = sum;
                else atomicAdd(&g_denom[(size_t)d * NHEAD + h], sum);
            }
        }
        __syncthreads();

        // ---- phase 6: segmented V reduce, warp per segment ----
        {
            int hh = head;
            for (int s = wid; s < ns; s += 8) {
                int st = seg_s[s];
                int d = dst_s[st];
                int gs = __ldg(&g_offs[d]), gend = __ldg(&g_offs[d + 1]);
                int lend = min(cnt, gend - e0);
                bool interior = (gs >= e0) && (gend <= e0 + cnt);
                float4 a4 = make_float4(0.f, 0.f, 0.f, 0.f);
                for (int e = st; e < lend; e++) {
                    float sce = ss_s[e];
                    float ww = w_sm[e * 8 + hh];
                    char* vrow = smc + OFF_KV + e * 512;
                    float4 vr = *(float4*)(vrow + (((unsigned)(lane * 16)) ^ ((unsigned)(e & 31) << 4)));
                    a4.x += fmaf(vr.x, sce, bv4.x) * ww;
                    a4.y += fmaf(vr.y, sce, bv4.y) * ww;
                    a4.z += fmaf(vr.z, sce, bv4.z) * ww;
                    a4.w += fmaf(vr.w, sce, bv4.w) * ww;
                }
                float* orow = out + (size_t)d * H + lane * 4;
                if (interior) *(float4*)orow = a4;
                else REDV4(orow, a4.x, a4.y, a4.z, a4.w);
            }
        }
        __syncthreads();
    }
}

// ---------------- normalize + re-zero hist ---------------------------------
__global__ void k_norm(float* __restrict__ out, int N)
{
    int idx = blockIdx.x * blockDim.x + threadIdx.x;
    if (idx < N) g_hist[idx] = 0;
    if (idx >= N * H) return;
    int n = idx >> 7, jj = idx & (H - 1);
    float dnm = g_denom[n * NHEAD + (jj >> 4)];
    float v = out[idx];
    out[idx] = (dnm > 0.f) ? v / dnm : 0.f;
}

// ---------------- launch ---------------------------------------------------
extern "C" void kernel_launch(void* const* d_in, const int* in_sizes, int n_in,
                              void* d_out, int out_size)
{
    const float* x     = (const float*)d_in[0];
    const float* ts    = (const float*)d_in[1];
    const int*   src   = (const int*)  d_in[2];
    const int*   dst   = (const int*)  d_in[3];
    const int*   etyp  = (const int*)  d_in[4];
    const float* etime = (const float*)d_in[5];
    const float* rel   = (const float*)d_in[6];
    const float* Wq    = (const float*)d_in[7];
    const float* bq    = (const float*)d_in[8];
    const float* Wk    = (const float*)d_in[9];
    const float* bk    = (const float*)d_in[10];
    const float* Wv    = (const float*)d_in[11];
    const float* bv    = (const float*)d_in[12];
    const float* W1    = (const float*)d_in[13];
    const float* b1    = (const float*)d_in[14];
    const float* W2    = (const float*)d_in[15];
    const float* b2    = (const float*)d_in[16];
    const float* tcp   = (const float*)d_in[17];

    int N    = in_sizes[0] / H;
    int E    = in_sizes[2];
    int NREL = in_sizes[6] / H;
    float* out = (float*)d_out;
    int ntiles = (E + TILE_E - 1) / TILE_E;

    int NB_SC = (E + 255) / 256;
    int NB_PW = 256;
    int NB_RL = (NREL + 1) / 2;
    int NB = NB_SC + NB_PW + NB_RL;

    static int smem_set = 0;
    if (!smem_set) {
        cudaFuncSetAttribute(k_edge_mma, cudaFuncAttributeMaxDynamicSharedMemorySize, SMEM_EDGE);
        cudaFuncSetAttribute(k_nodemma, cudaFuncAttributeMaxDynamicSharedMemorySize, SMEM_NODE);
        smem_set = 1;
    }

    k_pre1<<<2048, 256>>>(dst, out, N, E, out_size);
    k_scan<<<1, 1024>>>(N, E);
    k_pre3<<<NB, 256>>>(dst, Wq, W1, rel, Wk, Wv, N, E, NREL, NB_SC, NB_PW);
    k_nodemma<<<(N + 127) / 128, NTN, SMEM_NODE>>>(x, bq, N);
    k_edge_mma<<<296, NT, SMEM_EDGE>>>(x, ts, src, dst, etyp, etime, rel,
                                       bk, bv, b1, W2, b2, tcp, out, E, ntiles);
    k_norm<<<(N * H + 255) / 256, 256>>>(out, N);
}